// round 4
// baseline (speedup 1.0000x reference)
#include <cuda_runtime.h>

// Problem constants
#define Bn 8
#define Cc 16
#define Hh 128
#define Ww 128
#define PLANE (Bn*Cc*Hh*Ww)   // 2,097,152 floats per [B,C,H,W] stream

// Ping-pong stream buffers: [parity][row][stream(right,up,down)][B*C*H*W]
__device__ float g_buf[2u*4u*3u*(unsigned)PLANE];

// Dynamic smem layout:
//   s_in : 16 ch x 18x18 halo tile, each pixel stored DUPLICATED as float2{v,v}  (41472 B)
//   s_w  : [ci][k][co] weights, co contiguous                                    (27648 B)
#define SMEM_IN_BYTES  (16 * 324 * 8)
#define SMEM_W_BYTES   (16 * 9 * 48 * 4)
#define SMEM_TOTAL     (SMEM_IN_BYTES + SMEM_W_BYTES)

// One wavefront cell: y = relu(conv3x3(concat(in0,in1,in2), Wc) + bc); split into R/U/D.
// Null input slot == zeros == skip that 16-channel chunk entirely.
// Block: 16x16 spatial tile of one batch image. 256 threads:
//   thread = cog(4 out-channel groups of 12) x 64 pixel-slots (2x2 px each).
// Accumulators packed f32x2 over out-channel pairs; input packs read as pre-duplicated
// float2 pairs via LDS.128 (two dup-pairs per load); weights read 4 pairs per LDS.128.
__global__ __launch_bounds__(256, 2) void cell_kernel(
    const float* __restrict__ in0, const float* __restrict__ in1, const float* __restrict__ in2,
    const float* __restrict__ Wc, const float* __restrict__ bc,
    float* __restrict__ outR, float* __restrict__ outU, float* __restrict__ outD)
{
    extern __shared__ __align__(16) char smem_raw[];
    float2* s_in = reinterpret_cast<float2*>(smem_raw);                   // 16*324 float2
    float*  s_w  = reinterpret_cast<float*>(smem_raw + SMEM_IN_BYTES);    // 16*9*48 floats

    const int tid = threadIdx.x;
    const int cog = tid & 3;          // out-channel group 0..3 (12 co each)
    const int ps  = tid >> 2;         // pixel slot 0..63
    const int pby = ps >> 3, pbx = ps & 7;
    const int py0 = pby * 2, px0 = pbx * 2;     // 2x2 pixel block origin in tile
    const int gx0 = blockIdx.x * 16, gy0 = blockIdx.y * 16;
    const int bz  = blockIdx.z;
    const int cobase = cog * 12;

    unsigned long long acc[6][2][2];
    #pragma unroll
    for (int j = 0; j < 6; j++)
        #pragma unroll
        for (int py = 0; py < 2; py++)
            #pragma unroll
            for (int px = 0; px < 2; px++)
                acc[j][py][px] = 0ull;

    const float* srcs[3] = {in0, in1, in2};

    for (int chunk = 0; chunk < 3; chunk++) {
        const float* src = srcs[chunk];
        if (!src) continue;   // zero slot: contributes nothing (uniform branch)

        // ---- cooperative load: input tile (16 ch x 18 x 18, SAME halo), duplicated ----
        for (int e = tid; e < 16 * 324; e += 256) {
            int ci = e / 324; int r = e - ci * 324;
            int ty = r / 18;  int tx = r - ty * 18;
            int gy = gy0 - 1 + ty, gx = gx0 - 1 + tx;
            float v = 0.f;
            if ((unsigned)gy < 128u && (unsigned)gx < 128u)
                v = src[((bz * 16 + ci) * 128 + gy) * 128 + gx];
            s_in[e] = make_float2(v, v);   // STS.64 dup
        }
        // ---- cooperative load: weights, transposed to [ci][k][co] so co is contiguous ----
        for (int e = tid; e < 48 * 144; e += 256) {
            int co = e / 144; int r = e - co * 144;
            int ci = r / 9;   int k  = r - ci * 9;
            s_w[(ci * 9 + k) * 48 + co] = Wc[(co * 48 + chunk * 16 + ci) * 9 + k];
        }
        __syncthreads();

        // ---- compute: 16 input channels ----
        #pragma unroll 2
        for (int ci = 0; ci < 16; ci++) {
            // 4x4 input patch as 16 dup-pairs; each LDS.128 delivers two dup-pairs.
            unsigned long long xp[16];
            const ulonglong2* base =
                reinterpret_cast<const ulonglong2*>(&s_in[ci * 324 + py0 * 18 + px0]);
            #pragma unroll
            for (int dy = 0; dy < 4; dy++) {
                // row stride 18 float2 = 9 ulonglong2; base is 16B aligned (18*8B rows, px0 even)
                ulonglong2 a = base[dy * 9 + 0];   // dups for dx=0,1
                ulonglong2 b = base[dy * 9 + 1];   // dups for dx=2,3
                xp[dy * 4 + 0] = a.x; xp[dy * 4 + 1] = a.y;
                xp[dy * 4 + 2] = b.x; xp[dy * 4 + 3] = b.y;
            }
            #pragma unroll
            for (int k = 0; k < 9; k++) {
                const int ky = k / 3, kx = k - ky * 3;
                const ulonglong2* wrow =
                    reinterpret_cast<const ulonglong2*>(&s_w[(ci * 9 + k) * 48 + cobase]);
                unsigned long long wp[6];
                #pragma unroll
                for (int q = 0; q < 3; q++) {      // 3 x LDS.128 -> 6 weight pairs
                    ulonglong2 w2 = wrow[q];
                    wp[q * 2 + 0] = w2.x; wp[q * 2 + 1] = w2.y;
                }
                #pragma unroll
                for (int jp = 0; jp < 6; jp++) {
                    #pragma unroll
                    for (int py = 0; py < 2; py++)
                        #pragma unroll
                        for (int px = 0; px < 2; px++)
                            asm("fma.rn.f32x2 %0, %1, %2, %0;"
                                : "+l"(acc[jp][py][px])
                                : "l"(wp[jp]), "l"(xp[(py + ky) * 4 + (px + kx)]));
                }
            }
        }
        __syncthreads();
    }

    // ---- epilogue: bias + relu, split into right/up/down streams ----
    float* outs[3] = {outR, outU, outD};
    #pragma unroll
    for (int jp = 0; jp < 6; jp++) {
        int co0 = cobase + jp * 2;   // even; pair never straddles a stream boundary
        float b0 = bc[co0], b1 = bc[co0 + 1];
        int s0 = co0 >> 4, ch0 = co0 & 15;
        #pragma unroll
        for (int py = 0; py < 2; py++)
            #pragma unroll
            for (int px = 0; px < 2; px++) {
                float lo, hi;
                asm("mov.b64 {%0, %1}, %2;" : "=f"(lo), "=f"(hi) : "l"(acc[jp][py][px]));
                lo = fmaxf(lo + b0, 0.f);
                hi = fmaxf(hi + b1, 0.f);
                int gy = gy0 + py0 + py, gx = gx0 + px0 + px;
                float* o = outs[s0];
                o[((bz * 16 + ch0)     * 128 + gy) * 128 + gx] = lo;
                o[((bz * 16 + ch0 + 1) * 128 + gy) * 128 + gx] = hi;
            }
    }
}

extern "C" void kernel_launch(void* const* d_in, const int* in_sizes, int n_in,
                              void* d_out, int out_size)
{
    const float* x = (const float*)d_in[0];            // [8,16,128,128]
    const float* W = (const float*)d_in[1];            // [4,4,48,48,3,3]
    const float* b = (const float*)d_in[2];            // [4,4,48]
    float* out = (float*)d_out;                        // [8,16,128,128]

    static int attr_set = 0;
    if (!attr_set) {
        cudaFuncSetAttribute(cell_kernel,
                             cudaFuncAttributeMaxDynamicSharedMemorySize, SMEM_TOTAL);
        attr_set = 1;
    }

    float* buf = nullptr;
    cudaGetSymbolAddress((void**)&buf, g_buf);
    auto BUF = [&](int par, int row, int st) {
        return buf + (((size_t)par * 4 + row) * 3 + st) * (size_t)PLANE;
    };

    dim3 grid(8, 8, 8);   // (W tiles, H tiles, batch)
    dim3 block(256);

    // Wavefront: columns left->right, rows top->bottom (matches reference order).
    for (int col = 0; col < 4; col++) {
        int p = col & 1, q = p ^ 1;
        for (int row = 0; row < 4; row++) {
            const float *i0, *i1 = nullptr, *i2 = nullptr;
            if (col == 0) {
                i0 = (row == 0) ? x : BUF(p, row - 1, 2);         // down from above (this col)
            } else {
                i0 = BUF(q, row, 0);                              // right from prev col
                if (row == 0)       i1 = BUF(q, row + 1, 1);      // up from below (prev col)
                else if (row == 3)  i1 = BUF(p, row - 1, 2);      // down from above (this col)
                else {              i1 = BUF(q, row + 1, 1);
                                    i2 = BUF(p, row - 1, 2); }
            }
            float* oR = BUF(p, row, 0);
            float* oU = BUF(p, row, 1);
            float* oD = BUF(p, row, 2);
            if (col == 3 && row == 3) oR = out;   // final result = right stream of cell (3,3)

            const float* Wc = W + (size_t)(col * 4 + row) * 48 * 48 * 9;
            const float* bc = b + (size_t)(col * 4 + row) * 48;
            cell_kernel<<<grid, block, SMEM_TOTAL>>>(i0, i1, i2, Wc, bc, oR, oU, oD);
        }
    }
}

// round 5
// speedup vs baseline: 1.3721x; 1.3721x over previous
#include <cuda_runtime.h>

// Problem constants
#define PLANE (8*16*128*128)   // floats per [B=8,C=16,H=128,W=128] stream

// Ping-pong stream buffers: [parity][row][stream(right,up,down)]
__device__ float g_buf[2u*4u*3u*(unsigned)PLANE];

// Grid barrier state (generation-based; g_count self-resets each barrier)
__device__ unsigned g_count = 0;
__device__ volatile unsigned g_gen = 0;

__device__ __forceinline__ float* BUF(int par, int row, int st) {
    return g_buf + (((size_t)par * 4 + row) * 3 + st) * (size_t)PLANE;
}

__device__ __forceinline__ void grid_barrier(unsigned target) {
    __syncthreads();
    if (threadIdx.x == 0) {
        __threadfence();                       // release (+ L1 flush on sm_103a)
        if (atomicAdd(&g_count, 1u) == gridDim.x - 1) {
            g_count = 0;                       // safe: all arrived, none reading
            __threadfence();
            g_gen = target;
        } else {
            while (g_gen != target) __nanosleep(128);
        }
        __threadfence();                       // acquire: invalidate L1 before peer reads
    }
    __syncthreads();
}

// Persistent wavefront kernel. Levels f = 2*col + row (0..9); cells within a
// level are independent; level L cells are col in [c_min..c_max], row = L-2*col.
// Per job (= one 16x16 spatial tile of one cell): R1-style direct conv.
// 256 threads = 4 out-channel-groups(12 co) x 64 pixel slots (2x2 px).
__global__ __launch_bounds__(256, 2) void encoder_persistent(
    const float* __restrict__ x, const float* __restrict__ W,
    const float* __restrict__ bias, float* __restrict__ out)
{
    __shared__ float s_in[16 * 324];      // 16 ch x 18x18 halo tile (20.25 KB)
    __shared__ float s_w[16 * 9 * 48];    // [ci][k][co] (27 KB)

    const int tid = threadIdx.x;
    const int cog = tid & 3;
    const int ps  = tid >> 2;
    const int py0 = (ps >> 3) << 1, px0 = (ps & 7) << 1;
    const int cobase = cog * 12;

    unsigned gen = g_gen;   // launch-start generation (stable until barrier 1 completes)

    #pragma unroll 1
    for (int lvl = 0; lvl < 10; lvl++) {
        const int c_min = (lvl >= 2) ? ((lvl - 2) >> 1) : 0;
        const int c_hi  = lvl >> 1;
        const int c_max = (c_hi < 3) ? c_hi : 3;
        const int njobs = (c_max - c_min + 1) << 9;   // cells * 512 tiles

        #pragma unroll 1
        for (int j = blockIdx.x; j < njobs; j += gridDim.x) {
            const int c = c_min + (j >> 9);
            const int r = lvl - 2 * c;
            const int p = c & 1, q = p ^ 1;

            // --- per-cell input/output pointers (mirrors reference wavefront) ---
            const float *i0, *i1 = nullptr, *i2 = nullptr;
            if (c == 0) {
                i0 = (r == 0) ? x : BUF(p, r - 1, 2);
            } else {
                i0 = BUF(q, r, 0);
                if (r == 0)      i1 = BUF(q, 1, 1);
                else if (r == 3) i1 = BUF(p, 2, 2);
                else { i1 = BUF(q, r + 1, 1); i2 = BUF(p, r - 1, 2); }
            }
            float* oR = (c == 3 && r == 3) ? out : BUF(p, r, 0);
            float* oU = BUF(p, r, 1);
            float* oD = BUF(p, r, 2);
            const float* Wc = W + (size_t)(c * 4 + r) * (48 * 48 * 9);
            const float* bc = bias + (c * 4 + r) * 48;

            const int tile = j & 511;
            const int bz  = tile >> 6;
            const int gy0 = ((tile >> 3) & 7) << 4;
            const int gx0 = (tile & 7) << 4;

            // --- conv for this tile ---
            unsigned long long acc[6][2][2];
            #pragma unroll
            for (int jp = 0; jp < 6; jp++)
                #pragma unroll
                for (int py = 0; py < 2; py++)
                    #pragma unroll
                    for (int px = 0; px < 2; px++)
                        acc[jp][py][px] = 0ull;

            const float* srcs[3] = {i0, i1, i2};

            #pragma unroll 1
            for (int chunk = 0; chunk < 3; chunk++) {
                const float* src = srcs[chunk];
                if (!src) continue;   // zero slot: skip (uniform)

                // input tile (16ch x 18x18, SAME halo) — L2-direct loads (stream data)
                for (int e = tid; e < 16 * 324; e += 256) {
                    int ci = e / 324; int rr = e - ci * 324;
                    int ty = rr / 18; int tx = rr - ty * 18;
                    int gy = gy0 - 1 + ty, gx = gx0 - 1 + tx;
                    float v = 0.f;
                    if ((unsigned)gy < 128u && (unsigned)gx < 128u)
                        v = __ldcg(&src[((bz * 16 + ci) * 128 + gy) * 128 + gx]);
                    s_in[e] = v;
                }
                // weights transposed to [ci][k][co] (immutable -> normal cached loads)
                for (int e = tid; e < 48 * 144; e += 256) {
                    int co = e / 144; int rr = e - co * 144;
                    int ci = rr / 9;  int k  = rr - ci * 9;
                    s_w[(ci * 9 + k) * 48 + co] = Wc[(co * 48 + chunk * 16 + ci) * 9 + k];
                }
                __syncthreads();

                #pragma unroll 4
                for (int ci = 0; ci < 16; ci++) {
                    unsigned long long xp[16];
                    const float* base = &s_in[ci * 324 + py0 * 18 + px0];
                    #pragma unroll
                    for (int dy = 0; dy < 4; dy++)
                        #pragma unroll
                        for (int dx = 0; dx < 4; dx++) {
                            float v = base[dy * 18 + dx];
                            asm("mov.b64 %0, {%1, %1};" : "=l"(xp[dy * 4 + dx]) : "f"(v));
                        }
                    #pragma unroll
                    for (int k = 0; k < 9; k++) {
                        const int ky = k / 3, kx = k - ky * 3;
                        const unsigned long long* wrow =
                            reinterpret_cast<const unsigned long long*>(
                                &s_w[(ci * 9 + k) * 48 + cobase]);
                        #pragma unroll
                        for (int jp = 0; jp < 6; jp++) {
                            unsigned long long w = wrow[jp];   // LDS.64 co-pair
                            #pragma unroll
                            for (int py = 0; py < 2; py++)
                                #pragma unroll
                                for (int px = 0; px < 2; px++)
                                    asm("fma.rn.f32x2 %0, %1, %2, %0;"
                                        : "+l"(acc[jp][py][px])
                                        : "l"(w), "l"(xp[(py + ky) * 4 + (px + kx)]));
                        }
                    }
                }
                __syncthreads();
            }

            // --- epilogue: bias + relu, split into right/up/down streams ---
            float* outs[3] = {oR, oU, oD};
            #pragma unroll
            for (int jp = 0; jp < 6; jp++) {
                int co0 = cobase + jp * 2;
                float b0 = bc[co0], b1 = bc[co0 + 1];
                int s0 = co0 >> 4, ch0 = co0 & 15;
                #pragma unroll
                for (int py = 0; py < 2; py++)
                    #pragma unroll
                    for (int px = 0; px < 2; px++) {
                        float lo, hi;
                        asm("mov.b64 {%0, %1}, %2;"
                            : "=f"(lo), "=f"(hi) : "l"(acc[jp][py][px]));
                        lo = fmaxf(lo + b0, 0.f);
                        hi = fmaxf(hi + b1, 0.f);
                        int gy = gy0 + py0 + py, gx = gx0 + px0 + px;
                        float* o = outs[s0];
                        o[((bz * 16 + ch0)     * 128 + gy) * 128 + gx] = lo;
                        o[((bz * 16 + ch0 + 1) * 128 + gy) * 128 + gx] = hi;
                    }
            }
        }

        if (lvl < 9) { ++gen; grid_barrier(gen); }
    }
}

extern "C" void kernel_launch(void* const* d_in, const int* in_sizes, int n_in,
                              void* d_out, int out_size)
{
    const float* x = (const float*)d_in[0];            // [8,16,128,128]
    const float* W = (const float*)d_in[1];            // [4,4,48,48,3,3]
    const float* b = (const float*)d_in[2];            // [4,4,48]
    float* out = (float*)d_out;                        // [8,16,128,128]

    // Sized once on the (uncaptured) correctness run; constant thereafter.
    static int nblocks = 0;
    if (!nblocks) {
        int dev = 0; cudaGetDevice(&dev);
        int sms = 0; cudaDeviceGetAttribute(&sms, cudaDevAttrMultiProcessorCount, dev);
        int occ = 0;
        cudaOccupancyMaxActiveBlocksPerMultiprocessor(&occ, encoder_persistent, 256, 0);
        if (occ < 1) occ = 1;
        if (occ > 2) occ = 2;               // 2 CTAs/SM is the design point
        nblocks = sms * occ;                // all CTAs resident -> barrier is safe
    }

    encoder_persistent<<<nblocks, 256>>>(x, W, b, out);
}

// round 6
// speedup vs baseline: 1.3723x; 1.0001x over previous
#include <cuda_runtime.h>

// Problem constants
#define PLANE (8*16*128*128)   // floats per [B=8,C=16,H=128,W=128] stream

// Ping-pong stream buffers: [parity][row][stream(right,up,down)]
__device__ float g_buf[2u*4u*3u*(unsigned)PLANE];

// Grid barrier state (generation-based; g_count self-resets each barrier)
__device__ unsigned g_count = 0;
__device__ volatile unsigned g_gen = 0;

__device__ __forceinline__ float* BUF(int par, int row, int st) {
    return g_buf + (((size_t)par * 4 + row) * 3 + st) * (size_t)PLANE;
}

__device__ __forceinline__ void grid_barrier(unsigned target) {
    __syncthreads();
    if (threadIdx.x == 0) {
        __threadfence();                       // release (+ L1 flush on sm_103a)
        if (atomicAdd(&g_count, 1u) == gridDim.x - 1) {
            g_count = 0;                       // safe: all arrived, none reading
            __threadfence();
            g_gen = target;
        } else {
            while (g_gen != target) __nanosleep(128);
        }
        __threadfence();                       // acquire: invalidate L1 before peer reads
    }
    __syncthreads();
}

// Persistent wavefront kernel. Levels f = 2*col + row (0..9); cells within a
// level are independent; level L cells are col in [c_min..c_max], row = L-2*col.
// Per job (= one 16x16 spatial tile of one cell): R1-style direct conv.
// 256 threads = 4 out-channel-groups(12 co) x 64 pixel slots (2x2 px).
__global__ __launch_bounds__(256, 2) void encoder_persistent(
    const float* __restrict__ x, const float* __restrict__ W,
    const float* __restrict__ bias, float* __restrict__ out)
{
    __shared__ float s_in[16 * 324];      // 16 ch x 18x18 halo tile (20.25 KB)
    __shared__ float s_w[16 * 9 * 48];    // [ci][k][co] (27 KB)

    const int tid = threadIdx.x;
    const int cog = tid & 3;
    const int ps  = tid >> 2;
    const int py0 = (ps >> 3) << 1, px0 = (ps & 7) << 1;
    const int cobase = cog * 12;

    unsigned gen = g_gen;   // launch-start generation (stable until barrier 1 completes)

    #pragma unroll 1
    for (int lvl = 0; lvl < 10; lvl++) {
        const int c_min = (lvl >= 2) ? ((lvl - 2) >> 1) : 0;
        const int c_hi  = lvl >> 1;
        const int c_max = (c_hi < 3) ? c_hi : 3;
        const int njobs = (c_max - c_min + 1) << 9;   // cells * 512 tiles

        #pragma unroll 1
        for (int j = blockIdx.x; j < njobs; j += gridDim.x) {
            const int c = c_min + (j >> 9);
            const int r = lvl - 2 * c;
            const int p = c & 1, q = p ^ 1;

            // --- per-cell input/output pointers (mirrors reference wavefront) ---
            const float *i0, *i1 = nullptr, *i2 = nullptr;
            if (c == 0) {
                i0 = (r == 0) ? x : BUF(p, r - 1, 2);
            } else {
                i0 = BUF(q, r, 0);
                if (r == 0)      i1 = BUF(q, 1, 1);
                else if (r == 3) i1 = BUF(p, 2, 2);
                else { i1 = BUF(q, r + 1, 1); i2 = BUF(p, r - 1, 2); }
            }
            float* oR = (c == 3 && r == 3) ? out : BUF(p, r, 0);
            float* oU = BUF(p, r, 1);
            float* oD = BUF(p, r, 2);
            const float* Wc = W + (size_t)(c * 4 + r) * (48 * 48 * 9);
            const float* bc = bias + (c * 4 + r) * 48;

            const int tile = j & 511;
            const int bz  = tile >> 6;
            const int gy0 = ((tile >> 3) & 7) << 4;
            const int gx0 = (tile & 7) << 4;

            // --- conv for this tile ---
            unsigned long long acc[6][2][2];
            #pragma unroll
            for (int jp = 0; jp < 6; jp++)
                #pragma unroll
                for (int py = 0; py < 2; py++)
                    #pragma unroll
                    for (int px = 0; px < 2; px++)
                        acc[jp][py][px] = 0ull;

            const float* srcs[3] = {i0, i1, i2};

            #pragma unroll 1
            for (int chunk = 0; chunk < 3; chunk++) {
                const float* src = srcs[chunk];
                if (!src) continue;   // zero slot: skip (uniform)

                // input tile (16ch x 18x18, SAME halo) — L2-direct loads (stream data)
                for (int e = tid; e < 16 * 324; e += 256) {
                    int ci = e / 324; int rr = e - ci * 324;
                    int ty = rr / 18; int tx = rr - ty * 18;
                    int gy = gy0 - 1 + ty, gx = gx0 - 1 + tx;
                    float v = 0.f;
                    if ((unsigned)gy < 128u && (unsigned)gx < 128u)
                        v = __ldcg(&src[((bz * 16 + ci) * 128 + gy) * 128 + gx]);
                    s_in[e] = v;
                }
                // weights transposed to [ci][k][co] (immutable -> normal cached loads)
                for (int e = tid; e < 48 * 144; e += 256) {
                    int co = e / 144; int rr = e - co * 144;
                    int ci = rr / 9;  int k  = rr - ci * 9;
                    s_w[(ci * 9 + k) * 48 + co] = Wc[(co * 48 + chunk * 16 + ci) * 9 + k];
                }
                __syncthreads();

                #pragma unroll 4
                for (int ci = 0; ci < 16; ci++) {
                    unsigned long long xp[16];
                    const float* base = &s_in[ci * 324 + py0 * 18 + px0];
                    #pragma unroll
                    for (int dy = 0; dy < 4; dy++)
                        #pragma unroll
                        for (int dx = 0; dx < 4; dx++) {
                            float v = base[dy * 18 + dx];
                            asm("mov.b64 %0, {%1, %1};" : "=l"(xp[dy * 4 + dx]) : "f"(v));
                        }
                    #pragma unroll
                    for (int k = 0; k < 9; k++) {
                        const int ky = k / 3, kx = k - ky * 3;
                        const unsigned long long* wrow =
                            reinterpret_cast<const unsigned long long*>(
                                &s_w[(ci * 9 + k) * 48 + cobase]);
                        #pragma unroll
                        for (int jp = 0; jp < 6; jp++) {
                            unsigned long long w = wrow[jp];   // LDS.64 co-pair
                            #pragma unroll
                            for (int py = 0; py < 2; py++)
                                #pragma unroll
                                for (int px = 0; px < 2; px++)
                                    asm("fma.rn.f32x2 %0, %1, %2, %0;"
                                        : "+l"(acc[jp][py][px])
                                        : "l"(w), "l"(xp[(py + ky) * 4 + (px + kx)]));
                        }
                    }
                }
                __syncthreads();
            }

            // --- epilogue: bias + relu, split into right/up/down streams ---
            float* outs[3] = {oR, oU, oD};
            #pragma unroll
            for (int jp = 0; jp < 6; jp++) {
                int co0 = cobase + jp * 2;
                float b0 = bc[co0], b1 = bc[co0 + 1];
                int s0 = co0 >> 4, ch0 = co0 & 15;
                #pragma unroll
                for (int py = 0; py < 2; py++)
                    #pragma unroll
                    for (int px = 0; px < 2; px++) {
                        float lo, hi;
                        asm("mov.b64 {%0, %1}, %2;"
                            : "=f"(lo), "=f"(hi) : "l"(acc[jp][py][px]));
                        lo = fmaxf(lo + b0, 0.f);
                        hi = fmaxf(hi + b1, 0.f);
                        int gy = gy0 + py0 + py, gx = gx0 + px0 + px;
                        float* o = outs[s0];
                        o[((bz * 16 + ch0)     * 128 + gy) * 128 + gx] = lo;
                        o[((bz * 16 + ch0 + 1) * 128 + gy) * 128 + gx] = hi;
                    }
            }
        }

        if (lvl < 9) { ++gen; grid_barrier(gen); }
    }
}

extern "C" void kernel_launch(void* const* d_in, const int* in_sizes, int n_in,
                              void* d_out, int out_size)
{
    const float* x = (const float*)d_in[0];            // [8,16,128,128]
    const float* W = (const float*)d_in[1];            // [4,4,48,48,3,3]
    const float* b = (const float*)d_in[2];            // [4,4,48]
    float* out = (float*)d_out;                        // [8,16,128,128]

    // Sized once on the (uncaptured) correctness run; constant thereafter.
    static int nblocks = 0;
    if (!nblocks) {
        int dev = 0; cudaGetDevice(&dev);
        int sms = 0; cudaDeviceGetAttribute(&sms, cudaDevAttrMultiProcessorCount, dev);
        int occ = 0;
        cudaOccupancyMaxActiveBlocksPerMultiprocessor(&occ, encoder_persistent, 256, 0);
        if (occ < 1) occ = 1;
        if (occ > 2) occ = 2;               // 2 CTAs/SM is the design point
        nblocks = sms * occ;                // all CTAs resident -> barrier is safe
    }

    encoder_persistent<<<nblocks, 256>>>(x, W, b, out);
}